// round 1
// baseline (speedup 1.0000x reference)
#include <cuda_runtime.h>

// mixprop on GB300: h_{k+1} = alpha*x + (1-alpha) * (Aop @ h_k) per (b,c),
// out = sum_k W_k h_k + bias, accumulated in-place in d_out.
// Aop[w,v] = (adj[v,w] + I) / rowsum(adj[v,:]+I)  (row-normalized, transposed)

#define B_   16
#define C_   32
#define V_   512
#define L_   168
#define VL_  (V_ * L_)          // 86016
#define CVL_ (C_ * VL_)         // 2752512
#define TOT_ (B_ * CVL_)        // 44040192
#define ALPHA_ 0.05f
#define BETA_  0.95f

// Scratch ping-pong buffers for the propagation iterates (176 MB each).
__device__ float g_S1[TOT_];
__device__ float g_S2[TOT_];
// Normalized, transposed adjacency operator: g_A[w*V_ + v] = a[v][w].
__device__ float g_A[V_ * V_];

__device__ __forceinline__ const float* sel_buf(const float* ext, int sel) {
    return (sel == 1) ? g_S1 : (sel == 2) ? g_S2 : ext;
}

// ---------------------------------------------------------------------------
// Prep: build Aop. One block per row v (512 threads).
// ---------------------------------------------------------------------------
__global__ void prep_A(const float* __restrict__ adj) {
    int v = blockIdx.x;
    int t = threadIdx.x;
    __shared__ float red[V_];
    float val = adj[v * V_ + t];
    red[t] = val;
    __syncthreads();
    #pragma unroll
    for (int s = 256; s > 0; s >>= 1) {
        if (t < s) red[t] += red[t + s];
        __syncthreads();
    }
    float d = red[0] + 1.0f;   // rowsum(adj[v,:]) + identity
    float num = val + (t == v ? 1.0f : 0.0f);
    g_A[(size_t)t * V_ + v] = num / d;   // transposed store
}

// ---------------------------------------------------------------------------
// Propagation GEMM: D[b,c,w,l] = BETA * sum_v Aop[w,v] H[b,c,v,l] + ALPHA * x[b,c,w,l]
// Batched over 512 (b,c) pairs. Tile: BM=128 (w), BN=84 (l, 2 exact tiles), BK=32.
// 192 threads; per-thread register tile 8(w) x 7(l).
// ---------------------------------------------------------------------------
__global__ __launch_bounds__(192)
void prop_kernel(const float* __restrict__ Hext, int hsel,
                 const float* __restrict__ x, int dsel)
{
    const float* H = sel_buf(Hext, hsel);
    float* D = (dsel == 1) ? g_S1 : g_S2;

    int bc = blockIdx.z;
    const float* Hb = H + (size_t)bc * VL_;
    const float* xb = x + (size_t)bc * VL_;
    float*       Db = D + (size_t)bc * VL_;

    int w0 = blockIdx.y * 128;
    int l0 = blockIdx.x * 84;

    __shared__ float As[32][128];   // As[k][w]
    __shared__ float Bs[32][84];    // Bs[k][l]

    int tid = threadIdx.x;
    int lt  = tid % 12;             // 12 l-threads, 7 l each (strided by 12)
    int wt  = tid / 12;             // 16 w-threads, 8 w each (blocked)

    float acc[8][7];
    #pragma unroll
    for (int i = 0; i < 8; i++)
        #pragma unroll
        for (int j = 0; j < 7; j++) acc[i][j] = 0.0f;

    for (int k0 = 0; k0 < V_; k0 += 32) {
        // Load A tile: 128x32 = 1024 float4 groups of 4 -> 1024 f4? (1024 float4 total / 192 thr)
        #pragma unroll
        for (int i = 0; i < 6; i++) {
            int idx = tid + i * 192;          // 0..1151, valid < 1024
            if (idx < 1024) {
                int w = idx >> 3;
                int g = idx & 7;
                float4 a4 = *reinterpret_cast<const float4*>(
                    &g_A[(size_t)(w0 + w) * V_ + k0 + g * 4]);
                As[g * 4 + 0][w] = a4.x;
                As[g * 4 + 1][w] = a4.y;
                As[g * 4 + 2][w] = a4.z;
                As[g * 4 + 3][w] = a4.w;
            }
        }
        // Load B tile: 32x84 = 2688 floats / 192 thr = 14 each
        #pragma unroll
        for (int i = 0; i < 14; i++) {
            int idx = tid + i * 192;
            int k = idx / 84;
            int l = idx - k * 84;
            Bs[k][l] = Hb[(size_t)(k0 + k) * L_ + l0 + l];
        }
        __syncthreads();

        #pragma unroll
        for (int k = 0; k < 32; k++) {
            float a[8];
            float4 a0 = *reinterpret_cast<const float4*>(&As[k][wt * 8]);
            float4 a1 = *reinterpret_cast<const float4*>(&As[k][wt * 8 + 4]);
            a[0] = a0.x; a[1] = a0.y; a[2] = a0.z; a[3] = a0.w;
            a[4] = a1.x; a[5] = a1.y; a[6] = a1.z; a[7] = a1.w;
            float bv[7];
            #pragma unroll
            for (int m = 0; m < 7; m++) bv[m] = Bs[k][lt + 12 * m];
            #pragma unroll
            for (int i = 0; i < 8; i++)
                #pragma unroll
                for (int m = 0; m < 7; m++)
                    acc[i][m] += a[i] * bv[m];
        }
        __syncthreads();
    }

    // Epilogue: D = beta*acc + alpha*x
    #pragma unroll
    for (int i = 0; i < 8; i++) {
        int w = w0 + wt * 8 + i;
        #pragma unroll
        for (int m = 0; m < 7; m++) {
            int l = l0 + lt + 12 * m;
            size_t off = (size_t)w * L_ + l;
            Db[off] = BETA_ * acc[i][m] + ALPHA_ * xb[off];
        }
    }
}

// ---------------------------------------------------------------------------
// Channel mix + accumulate: out[b,o,r] (+)= bias[o] or += sum_c Wk[o,c] H[b,c,r]
// Wp points at W + k*32 (row stride 128). Each thread handles 2 positions.
// ---------------------------------------------------------------------------
__global__ __launch_bounds__(256)
void mix_acc(const float* __restrict__ Hext, int hsel,
             const float* __restrict__ Wp,
             const float* __restrict__ bias,
             float* __restrict__ out, int init)
{
    const float* H = sel_buf(Hext, hsel);
    __shared__ float Ws[32][32];
    __shared__ float bs[32];
    int tid = threadIdx.x;
    #pragma unroll
    for (int i = 0; i < 4; i++) {
        int idx = tid + i * 256;
        Ws[idx >> 5][idx & 31] = Wp[(idx >> 5) * 128 + (idx & 31)];
    }
    if (tid < 32) bs[tid] = bias[tid];
    __syncthreads();

    unsigned int q0 = blockIdx.x * 512u + tid;     // positions over B*VL (exact multiple)
    unsigned int q1 = q0 + 256u;
    unsigned int b0 = q0 / VL_, r0 = q0 % VL_;
    unsigned int b1 = q1 / VL_, r1 = q1 % VL_;

    const float* h0p = H + (size_t)b0 * CVL_ + r0;
    const float* h1p = H + (size_t)b1 * CVL_ + r1;
    float h0[32], h1[32];
    #pragma unroll
    for (int c = 0; c < 32; c++) {
        h0[c] = h0p[(size_t)c * VL_];
        h1[c] = h1p[(size_t)c * VL_];
    }
    float* o0p = out + (size_t)b0 * CVL_ + r0;
    float* o1p = out + (size_t)b1 * CVL_ + r1;

    #pragma unroll 4
    for (int o = 0; o < 32; o++) {
        float s0 = init ? bs[o] : o0p[(size_t)o * VL_];
        float s1 = init ? bs[o] : o1p[(size_t)o * VL_];
        #pragma unroll
        for (int c = 0; c < 32; c++) {
            float w = Ws[o][c];
            s0 += w * h0[c];
            s1 += w * h1[c];
        }
        o0p[(size_t)o * VL_] = s0;
        o1p[(size_t)o * VL_] = s1;
    }
}

// ---------------------------------------------------------------------------
extern "C" void kernel_launch(void* const* d_in, const int* in_sizes, int n_in,
                              void* d_out, int out_size) {
    const float* x   = (const float*)d_in[0];
    const float* adj = (const float*)d_in[1];
    const float* W   = (const float*)d_in[2];
    const float* b   = (const float*)d_in[3];
    float* out = (float*)d_out;

    (void)in_sizes; (void)n_in; (void)out_size;

    prep_A<<<V_, V_>>>(adj);

    dim3 pg(2, 4, B_ * C_);   // l-tiles, w-tiles, (b,c) batches
    const int MG = (B_ * VL_) / 512;  // 2688 blocks, 2 positions/thread

    // out = W_0 x + bias
    mix_acc<<<MG, 256>>>(x, 0, W + 0, b, out, 1);
    // h1 = alpha x + beta A x   -> S1
    prop_kernel<<<pg, 192>>>(x, 0, x, 1);
    mix_acc<<<MG, 256>>>(nullptr, 1, W + 32, b, out, 0);
    // h2 -> S2
    prop_kernel<<<pg, 192>>>(nullptr, 1, x, 2);
    mix_acc<<<MG, 256>>>(nullptr, 2, W + 64, b, out, 0);
    // h3 -> S1 (reuse)
    prop_kernel<<<pg, 192>>>(nullptr, 2, x, 1);
    mix_acc<<<MG, 256>>>(nullptr, 1, W + 96, b, out, 0);
}

// round 16
// speedup vs baseline: 2.9479x; 2.9479x over previous
#include <cuda_runtime.h>
#include <cstdint>

// mixprop: h_{k+1} = alpha*x + beta*(Aop @ h_k) per (b,c);  out = sum_k W_k h_k + bias
// Prop GEMM via mma.sync.m16n8k8.tf32 (baseline PTX -> compiles for compute_103;
// tcgen05 is rejected by this build's ptxas). Fused single channel-mix pass.

#define B_   16
#define C_   32
#define V_   512
#define L_   168
#define VL_  (V_ * L_)          // 86016
#define CVL_ (C_ * VL_)         // 2752512
#define TOT_ (B_ * CVL_)        // 44040192
#define ALPHA_ 0.05f
#define BETA_  0.95f

// Scratch iterate buffers (176 MB each) + normalized transposed adjacency.
__device__ float g_S1[TOT_];
__device__ float g_S2[TOT_];
__device__ float g_S3[TOT_];
__device__ float g_A[V_ * V_];   // g_A[w*V + v] = a[v][w], tf32-rounded

__device__ __forceinline__ float to_tf32(float f) {
    uint32_t u;
    asm("cvt.rna.tf32.f32 %0, %1;" : "=r"(u) : "f"(f));
    return __uint_as_float(u);
}

// mma.sync m16n8k8 tf32: D += A(16x8,row) * B(8x8,col)
__device__ __forceinline__ void mma8(float* c,
                                     uint32_t a0, uint32_t a1, uint32_t a2, uint32_t a3,
                                     uint32_t b0, uint32_t b1) {
    asm volatile(
        "mma.sync.aligned.m16n8k8.row.col.f32.tf32.tf32.f32 "
        "{%0,%1,%2,%3}, {%4,%5,%6,%7}, {%8,%9}, {%0,%1,%2,%3};"
        : "+f"(c[0]), "+f"(c[1]), "+f"(c[2]), "+f"(c[3])
        : "r"(a0), "r"(a1), "r"(a2), "r"(a3), "r"(b0), "r"(b1));
}

// ---------------------------------------------------------------------------
// Prep: row-normalize adj + I, transpose, round to tf32. One block per row v.
// ---------------------------------------------------------------------------
__global__ void prep_A(const float* __restrict__ adj) {
    int v = blockIdx.x;
    int t = threadIdx.x;
    __shared__ float red[V_];
    float val = adj[v * V_ + t];
    red[t] = val;
    __syncthreads();
    #pragma unroll
    for (int s = 256; s > 0; s >>= 1) {
        if (t < s) red[t] += red[t + s];
        __syncthreads();
    }
    float d = red[0] + 1.0f;
    float num = val + (t == v ? 1.0f : 0.0f);
    g_A[(size_t)t * V_ + v] = to_tf32(num / d);
}

// ---------------------------------------------------------------------------
// Propagation GEMM (tf32 mma.sync).
// CTA: M=128 (w-tile), N=168 (full L), K=512 in 16 chunks of 32.
// 384 threads = 12 warps as 4(M) x 3(N); warp tile 32x56 = 2 x 7 m16n8 tiles.
// D[w,l] = sum_v A[w,v] H[v,l];  epilogue: Db = beta*D + alpha*x.
// Grid = (4 w-tiles FASTEST, 512 bc): co-resident w-tiles share H via L2.
// ---------------------------------------------------------------------------
#define KC        32
#define NCHUNK    16
#define AS_STRIDE 36
#define A_FLOATS  (128 * AS_STRIDE)            // 4608
#define B_FLOATS  (L_ * AS_STRIDE)             // 6048
#define BUF_FLOATS (A_FLOATS + B_FLOATS)       // 10656
#define SMEM_BYTES (2 * BUF_FLOATS * 4)        // 85248

__global__ __launch_bounds__(384, 1)
void prop_tc(const float* __restrict__ Hext, int hsel,
             const float* __restrict__ x, int dsel)
{
    extern __shared__ float sm[];
    const float* H = (hsel == 1) ? g_S1 : (hsel == 2) ? g_S2 : Hext;
    float* D = (dsel == 1) ? g_S1 : (dsel == 2) ? g_S2 : g_S3;

    int w0 = blockIdx.x * 128;             // M-tile origin (fast dim -> L2 reuse of H)
    int bc = blockIdx.y;                   // 0..511 (b,c)
    const float* Hb = H + (size_t)bc * VL_;
    const float* xb = x + (size_t)bc * VL_;
    float*       Db = D + (size_t)bc * VL_;

    int tid = threadIdx.x;
    int lane = tid & 31;
    int wid  = tid >> 5;                   // 0..11
    int wm   = wid & 3;                    // M-group 0..3
    int wn   = wid >> 2;                   // N-group 0..2
    int m_base = wm * 32;
    int n_base = wn * 56;
    int g   = lane >> 2;                   // groupID 0..7
    int cc  = lane & 3;                    // threadID-in-group 0..3

    float acc[2][7][4];
    #pragma unroll
    for (int i = 0; i < 2; ++i)
        #pragma unroll
        for (int j = 0; j < 7; ++j)
            #pragma unroll
            for (int q = 0; q < 4; ++q) acc[i][j][q] = 0.0f;

    float4 pa[3];   // prefetch regs: A chunk (1024 float4 over 384 thr)
    float4 pb[4];   // prefetch regs: B chunk (1344 groups over 384 thr)

    // --- chunk loaders -----------------------------------------------------
    auto ldgA = [&](int k0) {
        #pragma unroll
        for (int i = 0; i < 3; ++i) {
            int j = tid + i * 384;
            if (j < 1024) {
                int r = j >> 3, gq = j & 7;
                pa[i] = *reinterpret_cast<const float4*>(
                    g_A + (size_t)(w0 + r) * V_ + k0 + gq * 4);
            }
        }
    };
    auto ldgB = [&](int k0) {
        #pragma unroll
        for (int i = 0; i < 4; ++i) {
            int j = tid + i * 384;
            if (j < 1344) {
                int v4 = (j / L_) * 4;       // 0,4,...,28
                int l  = j % L_;
                const float* hp = Hb + (size_t)(k0 + v4) * L_ + l;
                pb[i] = make_float4(hp[0], hp[L_], hp[2 * L_], hp[3 * L_]);
            }
        }
    };
    auto stsChunk = [&](int buf) {
        float* As = sm + buf * BUF_FLOATS;
        float* Bs = As + A_FLOATS;
        #pragma unroll
        for (int i = 0; i < 3; ++i) {
            int j = tid + i * 384;
            if (j < 1024) {
                int r = j >> 3, gq = j & 7;
                *reinterpret_cast<float4*>(As + r * AS_STRIDE + gq * 4) = pa[i];
            }
        }
        #pragma unroll
        for (int i = 0; i < 4; ++i) {
            int j = tid + i * 384;
            if (j < 1344) {
                int v4 = (j / L_) * 4;
                int l  = j % L_;
                float4 t = make_float4(to_tf32(pb[i].x), to_tf32(pb[i].y),
                                       to_tf32(pb[i].z), to_tf32(pb[i].w));
                *reinterpret_cast<float4*>(Bs + l * AS_STRIDE + v4) = t;
            }
        }
    };
    auto compute = [&](int buf) {
        const float* As = sm + buf * BUF_FLOATS;
        const float* Bs = As + A_FLOATS;
        #pragma unroll
        for (int kk = 0; kk < KC; kk += 8) {
            uint32_t af[2][4];
            #pragma unroll
            for (int mt = 0; mt < 2; ++mt) {
                const float* ap = As + (m_base + mt * 16 + g) * AS_STRIDE + kk + cc;
                af[mt][0] = __float_as_uint(ap[0]);
                af[mt][1] = __float_as_uint(ap[8 * AS_STRIDE]);
                af[mt][2] = __float_as_uint(ap[4]);
                af[mt][3] = __float_as_uint(ap[8 * AS_STRIDE + 4]);
            }
            #pragma unroll
            for (int nt = 0; nt < 7; ++nt) {
                const float* bp = Bs + (n_base + nt * 8 + g) * AS_STRIDE + kk + cc;
                uint32_t b0 = __float_as_uint(bp[0]);
                uint32_t b1 = __float_as_uint(bp[4]);
                mma8(acc[0][nt], af[0][0], af[0][1], af[0][2], af[0][3], b0, b1);
                mma8(acc[1][nt], af[1][0], af[1][1], af[1][2], af[1][3], b0, b1);
            }
        }
    };

    // --- pipelined mainloop ------------------------------------------------
    ldgA(0); ldgB(0);
    stsChunk(0);
    ldgA(KC); ldgB(KC);
    __syncthreads();

    for (int c = 0; c < NCHUNK; ++c) {
        if (c < NCHUNK - 1) stsChunk((c + 1) & 1);
        if (c < NCHUNK - 2) { ldgA((c + 2) * KC); ldgB((c + 2) * KC); }
        compute(c & 1);
        __syncthreads();
    }

    // --- epilogue: Db = beta*acc + alpha*x --------------------------------
    #pragma unroll
    for (int mt = 0; mt < 2; ++mt) {
        #pragma unroll
        for (int h = 0; h < 2; ++h) {
            int row = w0 + m_base + mt * 16 + h * 8 + g;
            const float* xr = xb + (size_t)row * L_;
            float*       dr = Db + (size_t)row * L_;
            #pragma unroll
            for (int nt = 0; nt < 7; ++nt) {
                int col = n_base + nt * 8 + cc * 2;
                float2 xv = *reinterpret_cast<const float2*>(xr + col);
                float2 ov;
                ov.x = BETA_ * acc[mt][nt][h * 2 + 0] + ALPHA_ * xv.x;
                ov.y = BETA_ * acc[mt][nt][h * 2 + 1] + ALPHA_ * xv.y;
                *reinterpret_cast<float2*>(dr + col) = ov;
            }
        }
    }
}

// ---------------------------------------------------------------------------
// Fused channel mix: out[b,o,r] = bias[o] + sum_s sum_c W[o, s*32+c] * Hs[b,c,r]
// over sources {x, S1, S2, S3}. One position per thread (regs ~80, no spills).
// ---------------------------------------------------------------------------
__global__ __launch_bounds__(256)
void mix_all(const float* __restrict__ x,
             const float* __restrict__ W,
             const float* __restrict__ bias,
             float* __restrict__ out)
{
    __shared__ float Wsm[32 * 128];
    __shared__ float bs[32];
    int tid = threadIdx.x;
    #pragma unroll
    for (int i = 0; i < 16; ++i) Wsm[tid + i * 256] = W[tid + i * 256];
    if (tid < 32) bs[tid] = bias[tid];
    __syncthreads();

    unsigned int p = blockIdx.x * 256u + tid;   // position in [0, B*VL)
    unsigned int b = p / VL_;
    unsigned int r = p - b * VL_;

    const float* srcs[4] = { x, g_S1, g_S2, g_S3 };

    float acc[32];
    #pragma unroll
    for (int o = 0; o < 32; ++o) acc[o] = bs[o];

    for (int s = 0; s < 4; ++s) {
        const float* Hs = srcs[s] + (size_t)b * CVL_ + r;
        float h[32];
        #pragma unroll
        for (int cch = 0; cch < 32; ++cch)
            h[cch] = Hs[(size_t)cch * VL_];

        #pragma unroll
        for (int o = 0; o < 32; ++o) {
            const float4* wr = reinterpret_cast<const float4*>(Wsm + o * 128 + s * 32);
            #pragma unroll
            for (int q = 0; q < 8; ++q) {
                float4 w4 = wr[q];
                acc[o] += w4.x * h[4 * q + 0] + w4.y * h[4 * q + 1]
                        + w4.z * h[4 * q + 2] + w4.w * h[4 * q + 3];
            }
        }
    }

    float* ob = out + (size_t)b * CVL_ + r;
    #pragma unroll
    for (int o = 0; o < 32; ++o)
        ob[(size_t)o * VL_] = acc[o];
}

// ---------------------------------------------------------------------------
extern "C" void kernel_launch(void* const* d_in, const int* in_sizes, int n_in,
                              void* d_out, int out_size) {
    const float* x   = (const float*)d_in[0];
    const float* adj = (const float*)d_in[1];
    const float* W   = (const float*)d_in[2];
    const float* b   = (const float*)d_in[3];
    float* out = (float*)d_out;
    (void)in_sizes; (void)n_in; (void)out_size;

    cudaFuncSetAttribute(prop_tc, cudaFuncAttributeMaxDynamicSharedMemorySize, SMEM_BYTES);

    prep_A<<<V_, V_>>>(adj);

    dim3 pg(4, C_ * B_);   // x = w-tile (fast -> co-resident share H), y = (b,c)
    prop_tc<<<pg, 384, SMEM_BYTES>>>(x, 0, x, 1);        // h1 -> S1
    prop_tc<<<pg, 384, SMEM_BYTES>>>(nullptr, 1, x, 2);  // h2 -> S2
    prop_tc<<<pg, 384, SMEM_BYTES>>>(nullptr, 2, x, 3);  // h3 -> S3

    mix_all<<<(B_ * VL_) / 256, 256>>>(x, W, b, out);
}